// round 8
// baseline (speedup 1.0000x reference)
#include <cuda_runtime.h>
#include <cuda.h>
#include <cstdint>
#include <math.h>

// ---------------------------------------------------------------------------
// ViT MHA B=8, S=1024, D=1024, H=16, hd=64 (fp32 in/out).
// R7: ldmatrix everywhere (4x fewer smem issues in mma loops); gemm converts
//     tiles to tf32 in-place once per k-chunk. Numerics identical to R6.
// ---------------------------------------------------------------------------

#define NB_HEADS 16
#define HEAD_DIM 64
#define SEQ 1024
#define BATCH 8
#define DMODEL 1024

__device__ float g_q[(size_t)BATCH * NB_HEADS * SEQ * HEAD_DIM];
__device__ float g_k[(size_t)BATCH * NB_HEADS * SEQ * HEAD_DIM];
__device__ float g_v[(size_t)BATCH * NB_HEADS * SEQ * HEAD_DIM];
__device__ float g_o[(size_t)BATCH * SEQ * DMODEL];
__device__ float g_wqkvT[(size_t)3072 * 1024];   // [N][K] K-major
__device__ float g_wprojT[(size_t)1024 * 1024];  // [N][K] K-major

// ------------------------------ helpers ------------------------------------
__device__ __forceinline__ uint32_t smem_u32(const void* p) {
    uint32_t a;
    asm("{ .reg .u64 t; cvta.to.shared.u64 t, %1; cvt.u32.u64 %0, t; }"
        : "=r"(a) : "l"(p));
    return a;
}

__device__ __forceinline__ uint32_t f2tf32(float f) {
    uint32_t u;
    asm("cvt.rna.tf32.f32 %0, %1;" : "=r"(u) : "f"(f));
    return u;
}

__device__ __forceinline__ void cp_async16(uint32_t dst, const void* src) {
    asm volatile("cp.async.ca.shared.global [%0], [%1], 16;"
                 :: "r"(dst), "l"(src) : "memory");
}
__device__ __forceinline__ void cp_commit() {
    asm volatile("cp.async.commit_group;" ::: "memory");
}
__device__ __forceinline__ void cp_wait0() {
    asm volatile("cp.async.wait_group 0;" ::: "memory");
}
__device__ __forceinline__ void cp_wait1() {
    asm volatile("cp.async.wait_group 1;" ::: "memory");
}

__device__ __forceinline__ void mma_tf32(float& c0, float& c1, float& c2, float& c3,
                                         uint32_t a0, uint32_t a1, uint32_t a2,
                                         uint32_t a3, uint32_t b0, uint32_t b1) {
    asm volatile(
        "mma.sync.aligned.m16n8k8.row.col.f32.tf32.tf32.f32 "
        "{%0,%1,%2,%3}, {%4,%5,%6,%7}, {%8,%9}, {%0,%1,%2,%3};"
        : "+f"(c0), "+f"(c1), "+f"(c2), "+f"(c3)
        : "r"(a0), "r"(a1), "r"(a2), "r"(a3), "r"(b0), "r"(b1));
}

// ldmatrix: four 8x8 b16 tiles == tf32 fragment quads on 32-bit data.
__device__ __forceinline__ void ldsm_x4(uint32_t& r0, uint32_t& r1,
                                        uint32_t& r2, uint32_t& r3, uint32_t a) {
    asm volatile("ldmatrix.sync.aligned.m8n8.x4.shared.b16 {%0,%1,%2,%3}, [%4];"
                 : "=r"(r0), "=r"(r1), "=r"(r2), "=r"(r3) : "r"(a));
}

// ---------------------------------------------------------------------------
// Weight transpose: out[n][k] = in[k][n].  in is [1024][C].
// ---------------------------------------------------------------------------
__global__ __launch_bounds__(256) void transpose_kernel(const float* __restrict__ in,
                                                        int C, int which) {
    __shared__ float t[32][33];
    float* out = which ? g_wprojT : g_wqkvT;
    const int R = 1024;
    const int c0 = blockIdx.x * 32, r0 = blockIdx.y * 32;
    const int tx = threadIdx.x, ty = threadIdx.y;  // 32 x 8
#pragma unroll
    for (int i = 0; i < 32; i += 8)
        t[ty + i][tx] = in[(size_t)(r0 + ty + i) * C + c0 + tx];
    __syncthreads();
#pragma unroll
    for (int i = 0; i < 32; i += 8)
        out[(size_t)(c0 + ty + i) * R + r0 + tx] = t[tx][ty + i];
}

// ---------------------------------------------------------------------------
// mma.sync tf32 GEMM: C[128x128] = A x BT^T, K=1024.
// R7: after each cp.async tile lands, one in-place fp32->tf32 pass, then the
// mma loop is pure ldmatrix + HMMA (no per-use cvt, 4x fewer smem issues).
// ---------------------------------------------------------------------------
#define PAD 36
#define GEMM_SMEM_BYTES (2 * 2 * 128 * PAD * 4)

__global__ __launch_bounds__(256) void gemm_mma(const float* __restrict__ A_ext,
                                                const float* __restrict__ bias,
                                                float* __restrict__ Cout, int mode) {
    extern __shared__ __align__(16) float sm[];
    float* As = sm;
    float* Bs = sm + 2 * 128 * PAD;
    const uint32_t sA = smem_u32(As), sB = smem_u32(Bs);

    const float* A  = mode ? g_o      : A_ext;
    const float* BT = mode ? g_wprojT : g_wqkvT;

    const int m0 = blockIdx.y * 128;
    const int n0 = blockIdx.x * 128;
    const int tid = threadIdx.x;
    const int warp = tid >> 5, lane = tid & 31;
    const int g = lane >> 2, tig = lane & 3;
    const int wm = (warp >> 2) * 64;
    const int wn = (warp & 3) * 32;

    // ldmatrix lane address components
    const int r8 = lane & 7, sub = lane >> 3;
    const int rowA = ((sub & 1) << 3) + r8;   // A-frag: m-row offset
    const int colA = (sub >> 1) << 2;         // A-frag: k-col offset
    const int rowB = ((sub >> 1) << 3) + r8;  // B-frag: n-row offset
    const int colB = (sub & 1) << 2;          // B-frag: k-col offset

    float c[4][4][4];
#pragma unroll
    for (int i = 0; i < 4; i++)
#pragma unroll
        for (int j = 0; j < 4; j++)
#pragma unroll
            for (int r = 0; r < 4; r++) c[i][j][r] = 0.f;

    auto prefetch = [&](int buf, int kc) {
        const float* Ag = A  + (size_t)m0 * 1024 + kc * 32;
        const float* Bg = BT + (size_t)n0 * 1024 + kc * 32;
        const uint32_t aBase = sA + buf * 128 * PAD * 4;
        const uint32_t bBase = sB + buf * 128 * PAD * 4;
#pragma unroll
        for (int i = 0; i < 4; i++) {
            const int idx = tid + i * 256;
            const int row = idx >> 3, c4 = idx & 7;
            const uint32_t so = (uint32_t)(row * PAD + c4 * 4) * 4;
            cp_async16(aBase + so, Ag + (size_t)row * 1024 + c4 * 4);
            cp_async16(bBase + so, Bg + (size_t)row * 1024 + c4 * 4);
        }
        cp_commit();
    };

    prefetch(0, 0);

    for (int kc = 0; kc < 32; kc++) {
        const int p = kc & 1;
        cp_wait0();
        __syncthreads();
        if (kc < 31) prefetch(p ^ 1, kc + 1);

        float* Ab = As + p * 128 * PAD;
        float* Bb = Bs + p * 128 * PAD;

        // in-place fp32 -> tf32 conversion of the landed tile
#pragma unroll
        for (int i = 0; i < 4; i++) {
            const int idx = tid + i * 256;
            const int row = idx >> 3, c4 = idx & 7;
            float4 va = *(float4*)&Ab[row * PAD + c4 * 4];
            *(uint4*)&Ab[row * PAD + c4 * 4] =
                make_uint4(f2tf32(va.x), f2tf32(va.y), f2tf32(va.z), f2tf32(va.w));
            float4 vb = *(float4*)&Bb[row * PAD + c4 * 4];
            *(uint4*)&Bb[row * PAD + c4 * 4] =
                make_uint4(f2tf32(vb.x), f2tf32(vb.y), f2tf32(vb.z), f2tf32(vb.w));
        }
        __syncthreads();

        const uint32_t aAb = sA + (uint32_t)(p * 128 * PAD + (wm + rowA) * PAD + colA) * 4;
        const uint32_t aBb = sB + (uint32_t)(p * 128 * PAD + (wn + rowB) * PAD + colB) * 4;

#pragma unroll
        for (int ks = 0; ks < 4; ks++) {
            const uint32_t ko = ks * 32;   // 8 words
            uint32_t a[4][4], b[4][2];
#pragma unroll
            for (int mt = 0; mt < 4; mt++)
                ldsm_x4(a[mt][0], a[mt][1], a[mt][2], a[mt][3],
                        aAb + (uint32_t)(mt * 16 * PAD) * 4 + ko);
#pragma unroll
            for (int ntp = 0; ntp < 2; ntp++)
                ldsm_x4(b[2 * ntp][0], b[2 * ntp][1], b[2 * ntp + 1][0],
                        b[2 * ntp + 1][1],
                        aBb + (uint32_t)(ntp * 16 * PAD) * 4 + ko);
#pragma unroll
            for (int mt = 0; mt < 4; mt++)
#pragma unroll
                for (int nt = 0; nt < 4; nt++)
                    mma_tf32(c[mt][nt][0], c[mt][nt][1], c[mt][nt][2], c[mt][nt][3],
                             a[mt][0], a[mt][1], a[mt][2], a[mt][3],
                             b[nt][0], b[nt][1]);
        }
        __syncthreads();
    }

#pragma unroll
    for (int mt = 0; mt < 4; mt++) {
#pragma unroll
        for (int nt = 0; nt < 4; nt++) {
            const int rowAo = m0 + wm + mt * 16 + g;
            const int rowBo = rowAo + 8;
            const int n = n0 + wn + nt * 8 + 2 * tig;
            const float b0 = bias[n], b1 = bias[n + 1];
            if (mode == 1) {
                *(float2*)(Cout + (size_t)rowAo * 1024 + n) =
                    make_float2(c[mt][nt][0] + b0, c[mt][nt][1] + b1);
                *(float2*)(Cout + (size_t)rowBo * 1024 + n) =
                    make_float2(c[mt][nt][2] + b0, c[mt][nt][3] + b1);
            } else {
                const int which = n >> 10;
                const int nm = n & 1023;
                const int h = nm >> 6, dd = nm & 63;
                float* dst = (which == 0) ? g_q : (which == 1) ? g_k : g_v;
                const float sc = (which == 0) ? 0.125f : 1.f;
                const int bA = rowAo >> 10, sAr = rowAo & 1023;
                const int bB = rowBo >> 10, sBr = rowBo & 1023;
                const size_t offA =
                    (((size_t)(bA * NB_HEADS + h) * SEQ) + sAr) * HEAD_DIM + dd;
                const size_t offB =
                    (((size_t)(bB * NB_HEADS + h) * SEQ) + sBr) * HEAD_DIM + dd;
                *(float2*)(dst + offA) =
                    make_float2((c[mt][nt][0] + b0) * sc, (c[mt][nt][1] + b1) * sc);
                *(float2*)(dst + offB) =
                    make_float2((c[mt][nt][2] + b0) * sc, (c[mt][nt][3] + b1) * sc);
            }
        }
    }
}

// ---------------------------------------------------------------------------
// Tensor-core flash attention, R7: pre-converted tf32 smem + ldmatrix loops.
// Block = (128 queries) x (b,h). 256 threads / 8 warps, warp owns 16 q-rows.
// ---------------------------------------------------------------------------
#define PADA 68
#define OFF_QH 0
#define OFF_QL (128 * PADA)
#define OFF_KH (2 * 128 * PADA)
#define OFF_KL (OFF_KH + 64 * PADA)
#define OFF_VT (OFF_KL + 64 * PADA)
#define OFF_PS (OFF_VT + 64 * PADA)
#define OFF_ST (OFF_PS + 128 * PADA)
#define ATTN_SMEM_BYTES ((OFF_ST + 2 * 128 * PADA) * 4)

__global__ __launch_bounds__(256, 1) void attn_mma() {
    extern __shared__ __align__(16) uint32_t smw[];
    uint32_t* Qh = smw + OFF_QH;
    uint32_t* Ql = smw + OFF_QL;
    uint32_t* Kh = smw + OFF_KH;
    uint32_t* Kl = smw + OFF_KL;
    uint32_t* Vt = smw + OFF_VT;
    uint32_t* Ps = smw + OFF_PS;
    float* St[2] = {(float*)(smw + OFF_ST), (float*)(smw + OFF_ST + 128 * PADA)};

    const int tid = threadIdx.x;
    const int warp = tid >> 5, lane = tid & 31;
    const int g = lane >> 2, tig = lane & 3;
    const int wb = warp * 16;

    // ldmatrix lane address components
    const int r8 = lane & 7, sub = lane >> 3;
    const int rowA = ((sub & 1) << 3) + r8;
    const int colA = (sub >> 1) << 2;
    const int rowB = ((sub >> 1) << 3) + r8;
    const int colB = (sub & 1) << 2;

    const int q0 = blockIdx.x * 128;
    const int h = blockIdx.y, b = blockIdx.z;
    const size_t bh = (size_t)(b * NB_HEADS + h) * SEQ * HEAD_DIM;
    const float* qb = g_q + bh;
    const float* kb = g_k + bh;
    const float* vb = g_v + bh;

    auto issue_tile = [&](int k0, float* Stp) {
        const uint32_t sSt = smem_u32(Stp);
#pragma unroll
        for (int i = 0; i < 4; i++) {
            const int idx = tid + i * 256;
            const int row = idx >> 4, c4 = idx & 15;
            cp_async16(sSt + (uint32_t)(row * PADA + c4 * 4) * 4,
                       kb + (size_t)(k0 + row) * 64 + c4 * 4);
        }
#pragma unroll
        for (int i = 0; i < 4; i++) {
            const int idx = tid + i * 256;
            const int row = idx >> 4, c4 = idx & 15;
            cp_async16(sSt + (uint32_t)((64 + row) * PADA + c4 * 4) * 4,
                       vb + (size_t)(k0 + row) * 64 + c4 * 4);
        }
        cp_commit();
    };

    // ---- prologue: stage raw Q into Ps region, prefetch tile 0 ----
    {
        float* Qstage = (float*)Ps;
        const uint32_t sQst = smem_u32(Qstage);
#pragma unroll
        for (int i = 0; i < 8; i++) {
            const int idx = tid + i * 256;
            const int row = idx >> 4, c4 = idx & 15;
            cp_async16(sQst + (uint32_t)(row * PADA + c4 * 4) * 4,
                       qb + (size_t)(q0 + row) * 64 + c4 * 4);
        }
        cp_commit();
        issue_tile(0, St[0]);
        cp_wait1();
        __syncthreads();
#pragma unroll
        for (int i = 0; i < 8; i++) {
            const int idx = tid + i * 256;
            const int row = idx >> 4, c4 = idx & 15;
            const float4 v = *(const float4*)&Qstage[row * PADA + c4 * 4];
            const int o4 = row * PADA + c4 * 4;
            uint32_t h0 = f2tf32(v.x), h1 = f2tf32(v.y);
            uint32_t h2 = f2tf32(v.z), h3 = f2tf32(v.w);
            Ql[o4 + 0] = f2tf32(v.x - __uint_as_float(h0));
            Ql[o4 + 1] = f2tf32(v.y - __uint_as_float(h1));
            Ql[o4 + 2] = f2tf32(v.z - __uint_as_float(h2));
            Ql[o4 + 3] = f2tf32(v.w - __uint_as_float(h3));
            Qh[o4 + 0] = h0; Qh[o4 + 1] = h1; Qh[o4 + 2] = h2; Qh[o4 + 3] = h3;
        }
    }

    // per-lane ldmatrix base addresses
    const uint32_t aQh = smem_u32(Qh) + (uint32_t)(((wb + rowA) * PADA + colA) * 4);
    const uint32_t aQl = smem_u32(Ql) + (uint32_t)(((wb + rowA) * PADA + colA) * 4);
    const uint32_t aPs = smem_u32(Ps) + (uint32_t)(((wb + rowA) * PADA + colA) * 4);
    const uint32_t aKh = smem_u32(Kh) + (uint32_t)((rowB * PADA + colB) * 4);
    const uint32_t aKl = smem_u32(Kl) + (uint32_t)((rowB * PADA + colB) * 4);
    const uint32_t aVt = smem_u32(Vt) + (uint32_t)((rowB * PADA + colB) * 4);

    float o[8][4];
#pragma unroll
    for (int nt = 0; nt < 8; nt++)
#pragma unroll
        for (int r = 0; r < 4; r++) o[nt][r] = 0.f;
    float m0 = -1e30f, m1 = -1e30f, l0 = 0.f, l1 = 0.f;

    for (int kb0 = 0; kb0 < 16; kb0++) {
        const int p = kb0 & 1;
        float* Stc = St[p];
        cp_wait0();
        __syncthreads();

        // convert K tile -> Kh/Kl (split tf32)
#pragma unroll
        for (int i = 0; i < 4; i++) {
            const int idx = tid + i * 256;
            const int row = idx & 63, c4 = idx >> 6;
            const float4 v = *(const float4*)&Stc[row * PADA + c4 * 4];
            const int o4 = row * PADA + c4 * 4;
            uint32_t h0 = f2tf32(v.x), h1 = f2tf32(v.y);
            uint32_t h2 = f2tf32(v.z), h3 = f2tf32(v.w);
            Kl[o4 + 0] = f2tf32(v.x - __uint_as_float(h0));
            Kl[o4 + 1] = f2tf32(v.y - __uint_as_float(h1));
            Kl[o4 + 2] = f2tf32(v.z - __uint_as_float(h2));
            Kl[o4 + 3] = f2tf32(v.w - __uint_as_float(h3));
            Kh[o4 + 0] = h0; Kh[o4 + 1] = h1; Kh[o4 + 2] = h2; Kh[o4 + 3] = h3;
        }
        // convert V tile -> Vt (transposed, plain tf32)
#pragma unroll
        for (int i = 0; i < 4; i++) {
            const int idx = tid + i * 256;
            const int row = idx & 63, c4 = idx >> 6;
            const float4 v = *(const float4*)&Stc[(64 + row) * PADA + c4 * 4];
            Vt[(c4 * 4 + 0) * PADA + row] = f2tf32(v.x);
            Vt[(c4 * 4 + 1) * PADA + row] = f2tf32(v.y);
            Vt[(c4 * 4 + 2) * PADA + row] = f2tf32(v.z);
            Vt[(c4 * 4 + 3) * PADA + row] = f2tf32(v.w);
        }

        if (kb0 < 15) issue_tile((kb0 + 1) * 64, St[p ^ 1]);
        __syncthreads();

        // ---- S = Q K^T (split-tf32: h*l + l*h + h*h), ldmatrix operands ----
        float s[8][4];
#pragma unroll
        for (int nt = 0; nt < 8; nt++)
#pragma unroll
            for (int r = 0; r < 4; r++) s[nt][r] = 0.f;

#pragma unroll
        for (int ks = 0; ks < 8; ks++) {
            const uint32_t ko = ks * 32;
            uint32_t ah0, ah1, ah2, ah3, al0, al1, al2, al3;
            ldsm_x4(ah0, ah1, ah2, ah3, aQh + ko);
            ldsm_x4(al0, al1, al2, al3, aQl + ko);
#pragma unroll
            for (int ntp = 0; ntp < 4; ntp++) {
                const uint32_t no = (uint32_t)(ntp * 16 * PADA) * 4 + ko;
                uint32_t bh0, bh1, bh2, bh3, bl0, bl1, bl2, bl3;
                ldsm_x4(bh0, bh1, bh2, bh3, aKh + no);
                ldsm_x4(bl0, bl1, bl2, bl3, aKl + no);
                const int n0t = 2 * ntp, n1t = 2 * ntp + 1;
                mma_tf32(s[n0t][0], s[n0t][1], s[n0t][2], s[n0t][3],
                         ah0, ah1, ah2, ah3, bl0, bl1);
                mma_tf32(s[n0t][0], s[n0t][1], s[n0t][2], s[n0t][3],
                         al0, al1, al2, al3, bh0, bh1);
                mma_tf32(s[n0t][0], s[n0t][1], s[n0t][2], s[n0t][3],
                         ah0, ah1, ah2, ah3, bh0, bh1);
                mma_tf32(s[n1t][0], s[n1t][1], s[n1t][2], s[n1t][3],
                         ah0, ah1, ah2, ah3, bl2, bl3);
                mma_tf32(s[n1t][0], s[n1t][1], s[n1t][2], s[n1t][3],
                         al0, al1, al2, al3, bh2, bh3);
                mma_tf32(s[n1t][0], s[n1t][1], s[n1t][2], s[n1t][3],
                         ah0, ah1, ah2, ah3, bh2, bh3);
            }
        }

        // ---- fragment online softmax ----
        float rmax0 = -1e30f, rmax1 = -1e30f;
#pragma unroll
        for (int nt = 0; nt < 8; nt++) {
            rmax0 = fmaxf(rmax0, fmaxf(s[nt][0], s[nt][1]));
            rmax1 = fmaxf(rmax1, fmaxf(s[nt][2], s[nt][3]));
        }
        rmax0 = fmaxf(rmax0, __shfl_xor_sync(0xffffffffu, rmax0, 1));
        rmax0 = fmaxf(rmax0, __shfl_xor_sync(0xffffffffu, rmax0, 2));
        rmax1 = fmaxf(rmax1, __shfl_xor_sync(0xffffffffu, rmax1, 1));
        rmax1 = fmaxf(rmax1, __shfl_xor_sync(0xffffffffu, rmax1, 2));

        const float mn0 = fmaxf(m0, rmax0), mn1 = fmaxf(m1, rmax1);
        const float corr0 = __expf(m0 - mn0), corr1 = __expf(m1 - mn1);
        m0 = mn0; m1 = mn1;

        float ls0 = 0.f, ls1 = 0.f;
#pragma unroll
        for (int nt = 0; nt < 8; nt++) {
            s[nt][0] = __expf(s[nt][0] - mn0);
            s[nt][1] = __expf(s[nt][1] - mn0);
            s[nt][2] = __expf(s[nt][2] - mn1);
            s[nt][3] = __expf(s[nt][3] - mn1);
            ls0 += s[nt][0] + s[nt][1];
            ls1 += s[nt][2] + s[nt][3];
        }
        ls0 += __shfl_xor_sync(0xffffffffu, ls0, 1);
        ls0 += __shfl_xor_sync(0xffffffffu, ls0, 2);
        ls1 += __shfl_xor_sync(0xffffffffu, ls1, 1);
        ls1 += __shfl_xor_sync(0xffffffffu, ls1, 2);
        l0 = l0 * corr0 + ls0;
        l1 = l1 * corr1 + ls1;

        // ---- stage P (tf32) in smem; warp-private rows ----
#pragma unroll
        for (int nt = 0; nt < 8; nt++) {
            *(uint2*)&Ps[(wb + g) * PADA + nt * 8 + 2 * tig] =
                make_uint2(f2tf32(s[nt][0]), f2tf32(s[nt][1]));
            *(uint2*)&Ps[(wb + g + 8) * PADA + nt * 8 + 2 * tig] =
                make_uint2(f2tf32(s[nt][2]), f2tf32(s[nt][3]));
        }
        __syncwarp();

        // rescale O
#pragma unroll
        for (int nt = 0; nt < 8; nt++) {
            o[nt][0] *= corr0; o[nt][1] *= corr0;
            o[nt][2] *= corr1; o[nt][3] *= corr1;
        }

        // ---- O += P V^T (plain tf32), ldmatrix operands ----
#pragma unroll
        for (int ks = 0; ks < 8; ks++) {
            const uint32_t ko = ks * 32;
            uint32_t a0, a1, a2, a3;
            ldsm_x4(a0, a1, a2, a3, aPs + ko);
#pragma unroll
            for (int ntp = 0; ntp < 4; ntp++) {
                uint32_t b0, b1, b2, b3;
                ldsm_x4(b0, b1, b2, b3,
                        aVt + (uint32_t)(ntp * 16 * PADA) * 4 + ko);
                mma_tf32(o[2 * ntp][0], o[2 * ntp][1], o[2 * ntp][2], o[2 * ntp][3],
                         a0, a1, a2, a3, b0, b1);
                mma_tf32(o[2 * ntp + 1][0], o[2 * ntp + 1][1],
                         o[2 * ntp + 1][2], o[2 * ntp + 1][3],
                         a0, a1, a2, a3, b2, b3);
            }
        }
    }

    // ---- epilogue ----
    const float il0 = 1.f / l0, il1 = 1.f / l1;
    const int r0 = q0 + wb + g, r1 = r0 + 8;
#pragma unroll
    for (int nt = 0; nt < 8; nt++) {
        const int col = h * HEAD_DIM + nt * 8 + 2 * tig;
        *(float2*)(g_o + ((size_t)b * SEQ + r0) * DMODEL + col) =
            make_float2(o[nt][0] * il0, o[nt][1] * il0);
        *(float2*)(g_o + ((size_t)b * SEQ + r1) * DMODEL + col) =
            make_float2(o[nt][2] * il1, o[nt][3] * il1);
    }
}

// ---------------------------------------------------------------------------

extern "C" void kernel_launch(void* const* d_in, const int* in_sizes, int n_in,
                              void* d_out, int out_size) {
    (void)in_sizes; (void)n_in; (void)out_size;
    const float* x      = (const float*)d_in[0];
    const float* w_qkv  = (const float*)d_in[1];
    const float* b_qkv  = (const float*)d_in[2];
    const float* w_proj = (const float*)d_in[3];
    const float* b_proj = (const float*)d_in[4];
    float* out = (float*)d_out;

    cudaFuncSetAttribute(gemm_mma, cudaFuncAttributeMaxDynamicSharedMemorySize,
                         GEMM_SMEM_BYTES);
    cudaFuncSetAttribute(attn_mma, cudaFuncAttributeMaxDynamicSharedMemorySize,
                         ATTN_SMEM_BYTES);

    transpose_kernel<<<dim3(96, 32), dim3(32, 8)>>>(w_qkv, 3072, 0);
    transpose_kernel<<<dim3(32, 32), dim3(32, 8)>>>(w_proj, 1024, 1);

    gemm_mma<<<dim3(24, 64), 256, GEMM_SMEM_BYTES>>>(x, b_qkv, nullptr, 0);

    attn_mma<<<dim3(SEQ / 128, NB_HEADS, BATCH), 256, ATTN_SMEM_BYTES>>>();

    gemm_mma<<<dim3(8, 64), 256, GEMM_SMEM_BYTES>>>(nullptr, b_proj, out, 1);
}

// round 9
// speedup vs baseline: 1.0404x; 1.0404x over previous
#include <cuda_runtime.h>
#include <cuda.h>
#include <cstdint>
#include <math.h>

// ---------------------------------------------------------------------------
// ViT MHA B=8, S=1024, D=1024, H=16, hd=64 (fp32 in/out).
// R8: gemm reverted to proven R6 variant; attn keeps ldmatrix but issues the
//     split-tf32 QK mmas in 3 interleaved passes (RAW chains broken).
// ---------------------------------------------------------------------------

#define NB_HEADS 16
#define HEAD_DIM 64
#define SEQ 1024
#define BATCH 8
#define DMODEL 1024

__device__ float g_q[(size_t)BATCH * NB_HEADS * SEQ * HEAD_DIM];
__device__ float g_k[(size_t)BATCH * NB_HEADS * SEQ * HEAD_DIM];
__device__ float g_v[(size_t)BATCH * NB_HEADS * SEQ * HEAD_DIM];
__device__ float g_o[(size_t)BATCH * SEQ * DMODEL];
__device__ float g_wqkvT[(size_t)3072 * 1024];   // [N][K] K-major
__device__ float g_wprojT[(size_t)1024 * 1024];  // [N][K] K-major

// ------------------------------ helpers ------------------------------------
__device__ __forceinline__ uint32_t smem_u32(const void* p) {
    uint32_t a;
    asm("{ .reg .u64 t; cvta.to.shared.u64 t, %1; cvt.u32.u64 %0, t; }"
        : "=r"(a) : "l"(p));
    return a;
}

__device__ __forceinline__ uint32_t f2tf32(float f) {
    uint32_t u;
    asm("cvt.rna.tf32.f32 %0, %1;" : "=r"(u) : "f"(f));
    return u;
}

__device__ __forceinline__ void cp_async16(uint32_t dst, const void* src) {
    asm volatile("cp.async.ca.shared.global [%0], [%1], 16;"
                 :: "r"(dst), "l"(src) : "memory");
}
__device__ __forceinline__ void cp_commit() {
    asm volatile("cp.async.commit_group;" ::: "memory");
}
__device__ __forceinline__ void cp_wait0() {
    asm volatile("cp.async.wait_group 0;" ::: "memory");
}
__device__ __forceinline__ void cp_wait1() {
    asm volatile("cp.async.wait_group 1;" ::: "memory");
}

__device__ __forceinline__ void mma_tf32(float& c0, float& c1, float& c2, float& c3,
                                         uint32_t a0, uint32_t a1, uint32_t a2,
                                         uint32_t a3, uint32_t b0, uint32_t b1) {
    asm volatile(
        "mma.sync.aligned.m16n8k8.row.col.f32.tf32.tf32.f32 "
        "{%0,%1,%2,%3}, {%4,%5,%6,%7}, {%8,%9}, {%0,%1,%2,%3};"
        : "+f"(c0), "+f"(c1), "+f"(c2), "+f"(c3)
        : "r"(a0), "r"(a1), "r"(a2), "r"(a3), "r"(b0), "r"(b1));
}

__device__ __forceinline__ void ldsm_x4(uint32_t& r0, uint32_t& r1,
                                        uint32_t& r2, uint32_t& r3, uint32_t a) {
    asm volatile("ldmatrix.sync.aligned.m8n8.x4.shared.b16 {%0,%1,%2,%3}, [%4];"
                 : "=r"(r0), "=r"(r1), "=r"(r2), "=r"(r3) : "r"(a));
}

// ---------------------------------------------------------------------------
// Weight transpose: out[n][k] = in[k][n].  in is [1024][C].
// ---------------------------------------------------------------------------
__global__ __launch_bounds__(256) void transpose_kernel(const float* __restrict__ in,
                                                        int C, int which) {
    __shared__ float t[32][33];
    float* out = which ? g_wprojT : g_wqkvT;
    const int R = 1024;
    const int c0 = blockIdx.x * 32, r0 = blockIdx.y * 32;
    const int tx = threadIdx.x, ty = threadIdx.y;  // 32 x 8
#pragma unroll
    for (int i = 0; i < 32; i += 8)
        t[ty + i][tx] = in[(size_t)(r0 + ty + i) * C + c0 + tx];
    __syncthreads();
#pragma unroll
    for (int i = 0; i < 32; i += 8)
        out[(size_t)(c0 + ty + i) * R + r0 + tx] = t[tx][ty + i];
}

// ---------------------------------------------------------------------------
// mma.sync tf32 GEMM (R6 proven variant): C[128x128] = A x BT^T, K=1024.
// ---------------------------------------------------------------------------
#define PAD 36
#define GEMM_SMEM_BYTES (2 * 2 * 128 * PAD * 4)

__global__ __launch_bounds__(256) void gemm_mma(const float* __restrict__ A_ext,
                                                const float* __restrict__ bias,
                                                float* __restrict__ Cout, int mode) {
    extern __shared__ __align__(16) float sm[];
    float* As = sm;
    float* Bs = sm + 2 * 128 * PAD;
    const uint32_t sA = smem_u32(As), sB = smem_u32(Bs);

    const float* A  = mode ? g_o      : A_ext;
    const float* BT = mode ? g_wprojT : g_wqkvT;

    const int m0 = blockIdx.y * 128;
    const int n0 = blockIdx.x * 128;
    const int tid = threadIdx.x;
    const int warp = tid >> 5, lane = tid & 31;
    const int g = lane >> 2, tig = lane & 3;
    const int wm = (warp >> 2) * 64;
    const int wn = (warp & 3) * 32;

    float c[4][4][4];
#pragma unroll
    for (int i = 0; i < 4; i++)
#pragma unroll
        for (int j = 0; j < 4; j++)
#pragma unroll
            for (int r = 0; r < 4; r++) c[i][j][r] = 0.f;

    auto prefetch = [&](int buf, int kc) {
        const float* Ag = A  + (size_t)m0 * 1024 + kc * 32;
        const float* Bg = BT + (size_t)n0 * 1024 + kc * 32;
        const uint32_t aBase = sA + buf * 128 * PAD * 4;
        const uint32_t bBase = sB + buf * 128 * PAD * 4;
#pragma unroll
        for (int i = 0; i < 4; i++) {
            const int idx = tid + i * 256;
            const int row = idx >> 3, c4 = idx & 7;
            const uint32_t so = (uint32_t)(row * PAD + c4 * 4) * 4;
            cp_async16(aBase + so, Ag + (size_t)row * 1024 + c4 * 4);
            cp_async16(bBase + so, Bg + (size_t)row * 1024 + c4 * 4);
        }
        cp_commit();
    };

    prefetch(0, 0);

    for (int kc = 0; kc < 32; kc++) {
        const int p = kc & 1;
        cp_wait0();
        __syncthreads();
        if (kc < 31) prefetch(p ^ 1, kc + 1);

        const float* Ab = As + p * 128 * PAD;
        const float* Bb = Bs + p * 128 * PAD;

#pragma unroll
        for (int ks = 0; ks < 4; ks++) {
            const int kk = ks * 8;
            uint32_t a[4][4], b[4][2];
#pragma unroll
            for (int mt = 0; mt < 4; mt++) {
                const int r0 = wm + mt * 16 + g;
                a[mt][0] = f2tf32(Ab[r0 * PAD + kk + tig]);
                a[mt][1] = f2tf32(Ab[(r0 + 8) * PAD + kk + tig]);
                a[mt][2] = f2tf32(Ab[r0 * PAD + kk + tig + 4]);
                a[mt][3] = f2tf32(Ab[(r0 + 8) * PAD + kk + tig + 4]);
            }
#pragma unroll
            for (int nt = 0; nt < 4; nt++) {
                const int nr = wn + nt * 8 + g;
                b[nt][0] = f2tf32(Bb[nr * PAD + kk + tig]);
                b[nt][1] = f2tf32(Bb[nr * PAD + kk + tig + 4]);
            }
#pragma unroll
            for (int mt = 0; mt < 4; mt++)
#pragma unroll
                for (int nt = 0; nt < 4; nt++)
                    mma_tf32(c[mt][nt][0], c[mt][nt][1], c[mt][nt][2], c[mt][nt][3],
                             a[mt][0], a[mt][1], a[mt][2], a[mt][3],
                             b[nt][0], b[nt][1]);
        }
        __syncthreads();
    }

#pragma unroll
    for (int mt = 0; mt < 4; mt++) {
#pragma unroll
        for (int nt = 0; nt < 4; nt++) {
            const int rowA = m0 + wm + mt * 16 + g;
            const int rowB = rowA + 8;
            const int n = n0 + wn + nt * 8 + 2 * tig;
            const float b0 = bias[n], b1 = bias[n + 1];
            if (mode == 1) {
                *(float2*)(Cout + (size_t)rowA * 1024 + n) =
                    make_float2(c[mt][nt][0] + b0, c[mt][nt][1] + b1);
                *(float2*)(Cout + (size_t)rowB * 1024 + n) =
                    make_float2(c[mt][nt][2] + b0, c[mt][nt][3] + b1);
            } else {
                const int which = n >> 10;
                const int nm = n & 1023;
                const int h = nm >> 6, dd = nm & 63;
                float* dst = (which == 0) ? g_q : (which == 1) ? g_k : g_v;
                const float sc = (which == 0) ? 0.125f : 1.f;
                const int bA = rowA >> 10, sAr = rowA & 1023;
                const int bB = rowB >> 10, sBr = rowB & 1023;
                const size_t offA =
                    (((size_t)(bA * NB_HEADS + h) * SEQ) + sAr) * HEAD_DIM + dd;
                const size_t offB =
                    (((size_t)(bB * NB_HEADS + h) * SEQ) + sBr) * HEAD_DIM + dd;
                *(float2*)(dst + offA) =
                    make_float2((c[mt][nt][0] + b0) * sc, (c[mt][nt][1] + b1) * sc);
                *(float2*)(dst + offB) =
                    make_float2((c[mt][nt][2] + b0) * sc, (c[mt][nt][3] + b1) * sc);
            }
        }
    }
}

// ---------------------------------------------------------------------------
// Tensor-core flash attention, R8: ldmatrix operands + chain-broken mma order.
// Block = (128 queries) x (b,h). 256 threads / 8 warps, warp owns 16 q-rows.
// ---------------------------------------------------------------------------
#define PADA 68
#define OFF_QH 0
#define OFF_QL (128 * PADA)
#define OFF_KH (2 * 128 * PADA)
#define OFF_KL (OFF_KH + 64 * PADA)
#define OFF_VT (OFF_KL + 64 * PADA)
#define OFF_PS (OFF_VT + 64 * PADA)
#define OFF_ST (OFF_PS + 128 * PADA)
#define ATTN_SMEM_BYTES ((OFF_ST + 2 * 128 * PADA) * 4)

__global__ __launch_bounds__(256, 1) void attn_mma() {
    extern __shared__ __align__(16) uint32_t smw[];
    uint32_t* Qh = smw + OFF_QH;
    uint32_t* Ql = smw + OFF_QL;
    uint32_t* Kh = smw + OFF_KH;
    uint32_t* Kl = smw + OFF_KL;
    uint32_t* Vt = smw + OFF_VT;
    uint32_t* Ps = smw + OFF_PS;
    float* St[2] = {(float*)(smw + OFF_ST), (float*)(smw + OFF_ST + 128 * PADA)};

    const int tid = threadIdx.x;
    const int warp = tid >> 5, lane = tid & 31;
    const int g = lane >> 2, tig = lane & 3;
    const int wb = warp * 16;

    // ldmatrix lane address components
    const int r8 = lane & 7, sub = lane >> 3;
    const int rowA = ((sub & 1) << 3) + r8;
    const int colA = (sub >> 1) << 2;
    const int rowB = ((sub >> 1) << 3) + r8;
    const int colB = (sub & 1) << 2;

    const int q0 = blockIdx.x * 128;
    const int h = blockIdx.y, b = blockIdx.z;
    const size_t bh = (size_t)(b * NB_HEADS + h) * SEQ * HEAD_DIM;
    const float* qb = g_q + bh;
    const float* kb = g_k + bh;
    const float* vb = g_v + bh;

    auto issue_tile = [&](int k0, float* Stp) {
        const uint32_t sSt = smem_u32(Stp);
#pragma unroll
        for (int i = 0; i < 4; i++) {
            const int idx = tid + i * 256;
            const int row = idx >> 4, c4 = idx & 15;
            cp_async16(sSt + (uint32_t)(row * PADA + c4 * 4) * 4,
                       kb + (size_t)(k0 + row) * 64 + c4 * 4);
        }
#pragma unroll
        for (int i = 0; i < 4; i++) {
            const int idx = tid + i * 256;
            const int row = idx >> 4, c4 = idx & 15;
            cp_async16(sSt + (uint32_t)((64 + row) * PADA + c4 * 4) * 4,
                       vb + (size_t)(k0 + row) * 64 + c4 * 4);
        }
        cp_commit();
    };

    // ---- prologue: stage raw Q into Ps region, prefetch tile 0 ----
    {
        float* Qstage = (float*)Ps;
        const uint32_t sQst = smem_u32(Qstage);
#pragma unroll
        for (int i = 0; i < 8; i++) {
            const int idx = tid + i * 256;
            const int row = idx >> 4, c4 = idx & 15;
            cp_async16(sQst + (uint32_t)(row * PADA + c4 * 4) * 4,
                       qb + (size_t)(q0 + row) * 64 + c4 * 4);
        }
        cp_commit();
        issue_tile(0, St[0]);
        cp_wait1();
        __syncthreads();
#pragma unroll
        for (int i = 0; i < 8; i++) {
            const int idx = tid + i * 256;
            const int row = idx >> 4, c4 = idx & 15;
            const float4 v = *(const float4*)&Qstage[row * PADA + c4 * 4];
            const int o4 = row * PADA + c4 * 4;
            uint32_t h0 = f2tf32(v.x), h1 = f2tf32(v.y);
            uint32_t h2 = f2tf32(v.z), h3 = f2tf32(v.w);
            Ql[o4 + 0] = f2tf32(v.x - __uint_as_float(h0));
            Ql[o4 + 1] = f2tf32(v.y - __uint_as_float(h1));
            Ql[o4 + 2] = f2tf32(v.z - __uint_as_float(h2));
            Ql[o4 + 3] = f2tf32(v.w - __uint_as_float(h3));
            Qh[o4 + 0] = h0; Qh[o4 + 1] = h1; Qh[o4 + 2] = h2; Qh[o4 + 3] = h3;
        }
    }

    // per-lane ldmatrix base addresses
    const uint32_t aQh = smem_u32(Qh) + (uint32_t)(((wb + rowA) * PADA + colA) * 4);
    const uint32_t aQl = smem_u32(Ql) + (uint32_t)(((wb + rowA) * PADA + colA) * 4);
    const uint32_t aPs = smem_u32(Ps) + (uint32_t)(((wb + rowA) * PADA + colA) * 4);
    const uint32_t aKh = smem_u32(Kh) + (uint32_t)((rowB * PADA + colB) * 4);
    const uint32_t aKl = smem_u32(Kl) + (uint32_t)((rowB * PADA + colB) * 4);
    const uint32_t aVt = smem_u32(Vt) + (uint32_t)((rowB * PADA + colB) * 4);

    float o[8][4];
#pragma unroll
    for (int nt = 0; nt < 8; nt++)
#pragma unroll
        for (int r = 0; r < 4; r++) o[nt][r] = 0.f;
    float m0 = -1e30f, m1 = -1e30f, l0 = 0.f, l1 = 0.f;

    for (int kb0 = 0; kb0 < 16; kb0++) {
        const int p = kb0 & 1;
        float* Stc = St[p];
        cp_wait0();
        __syncthreads();

        // convert K tile -> Kh/Kl (split tf32)
#pragma unroll
        for (int i = 0; i < 4; i++) {
            const int idx = tid + i * 256;
            const int row = idx & 63, c4 = idx >> 6;
            const float4 v = *(const float4*)&Stc[row * PADA + c4 * 4];
            const int o4 = row * PADA + c4 * 4;
            uint32_t h0 = f2tf32(v.x), h1 = f2tf32(v.y);
            uint32_t h2 = f2tf32(v.z), h3 = f2tf32(v.w);
            Kl[o4 + 0] = f2tf32(v.x - __uint_as_float(h0));
            Kl[o4 + 1] = f2tf32(v.y - __uint_as_float(h1));
            Kl[o4 + 2] = f2tf32(v.z - __uint_as_float(h2));
            Kl[o4 + 3] = f2tf32(v.w - __uint_as_float(h3));
            Kh[o4 + 0] = h0; Kh[o4 + 1] = h1; Kh[o4 + 2] = h2; Kh[o4 + 3] = h3;
        }
        // convert V tile -> Vt (transposed, plain tf32)
#pragma unroll
        for (int i = 0; i < 4; i++) {
            const int idx = tid + i * 256;
            const int row = idx & 63, c4 = idx >> 6;
            const float4 v = *(const float4*)&Stc[(64 + row) * PADA + c4 * 4];
            Vt[(c4 * 4 + 0) * PADA + row] = f2tf32(v.x);
            Vt[(c4 * 4 + 1) * PADA + row] = f2tf32(v.y);
            Vt[(c4 * 4 + 2) * PADA + row] = f2tf32(v.z);
            Vt[(c4 * 4 + 3) * PADA + row] = f2tf32(v.w);
        }

        if (kb0 < 15) issue_tile((kb0 + 1) * 64, St[p ^ 1]);
        __syncthreads();

        // ---- S = Q K^T (split-tf32), chain-broken issue order ----
        float s[8][4];
#pragma unroll
        for (int nt = 0; nt < 8; nt++)
#pragma unroll
            for (int r = 0; r < 4; r++) s[nt][r] = 0.f;

#pragma unroll
        for (int ks = 0; ks < 8; ks++) {
            const uint32_t ko = ks * 32;
            uint32_t ah0, ah1, ah2, ah3, al0, al1, al2, al3;
            ldsm_x4(ah0, ah1, ah2, ah3, aQh + ko);
            ldsm_x4(al0, al1, al2, al3, aQl + ko);
            uint32_t kh[4][4], kl[4][4];
#pragma unroll
            for (int ntp = 0; ntp < 4; ntp++) {
                const uint32_t no = (uint32_t)(ntp * 16 * PADA) * 4 + ko;
                ldsm_x4(kh[ntp][0], kh[ntp][1], kh[ntp][2], kh[ntp][3], aKh + no);
                ldsm_x4(kl[ntp][0], kl[ntp][1], kl[ntp][2], kl[ntp][3], aKl + no);
            }
            // pass 1: ah * kl   (each accumulator touched once per pass)
#pragma unroll
            for (int ntp = 0; ntp < 4; ntp++) {
                mma_tf32(s[2 * ntp][0], s[2 * ntp][1], s[2 * ntp][2], s[2 * ntp][3],
                         ah0, ah1, ah2, ah3, kl[ntp][0], kl[ntp][1]);
                mma_tf32(s[2 * ntp + 1][0], s[2 * ntp + 1][1],
                         s[2 * ntp + 1][2], s[2 * ntp + 1][3],
                         ah0, ah1, ah2, ah3, kl[ntp][2], kl[ntp][3]);
            }
            // pass 2: al * kh
#pragma unroll
            for (int ntp = 0; ntp < 4; ntp++) {
                mma_tf32(s[2 * ntp][0], s[2 * ntp][1], s[2 * ntp][2], s[2 * ntp][3],
                         al0, al1, al2, al3, kh[ntp][0], kh[ntp][1]);
                mma_tf32(s[2 * ntp + 1][0], s[2 * ntp + 1][1],
                         s[2 * ntp + 1][2], s[2 * ntp + 1][3],
                         al0, al1, al2, al3, kh[ntp][2], kh[ntp][3]);
            }
            // pass 3: ah * kh
#pragma unroll
            for (int ntp = 0; ntp < 4; ntp++) {
                mma_tf32(s[2 * ntp][0], s[2 * ntp][1], s[2 * ntp][2], s[2 * ntp][3],
                         ah0, ah1, ah2, ah3, kh[ntp][0], kh[ntp][1]);
                mma_tf32(s[2 * ntp + 1][0], s[2 * ntp + 1][1],
                         s[2 * ntp + 1][2], s[2 * ntp + 1][3],
                         ah0, ah1, ah2, ah3, kh[ntp][2], kh[ntp][3]);
            }
        }

        // ---- fragment online softmax ----
        float rmax0 = -1e30f, rmax1 = -1e30f;
#pragma unroll
        for (int nt = 0; nt < 8; nt++) {
            rmax0 = fmaxf(rmax0, fmaxf(s[nt][0], s[nt][1]));
            rmax1 = fmaxf(rmax1, fmaxf(s[nt][2], s[nt][3]));
        }
        rmax0 = fmaxf(rmax0, __shfl_xor_sync(0xffffffffu, rmax0, 1));
        rmax0 = fmaxf(rmax0, __shfl_xor_sync(0xffffffffu, rmax0, 2));
        rmax1 = fmaxf(rmax1, __shfl_xor_sync(0xffffffffu, rmax1, 1));
        rmax1 = fmaxf(rmax1, __shfl_xor_sync(0xffffffffu, rmax1, 2));

        const float mn0 = fmaxf(m0, rmax0), mn1 = fmaxf(m1, rmax1);
        const float corr0 = __expf(m0 - mn0), corr1 = __expf(m1 - mn1);
        m0 = mn0; m1 = mn1;

        float ls0 = 0.f, ls1 = 0.f;
#pragma unroll
        for (int nt = 0; nt < 8; nt++) {
            s[nt][0] = __expf(s[nt][0] - mn0);
            s[nt][1] = __expf(s[nt][1] - mn0);
            s[nt][2] = __expf(s[nt][2] - mn1);
            s[nt][3] = __expf(s[nt][3] - mn1);
            ls0 += s[nt][0] + s[nt][1];
            ls1 += s[nt][2] + s[nt][3];
        }
        ls0 += __shfl_xor_sync(0xffffffffu, ls0, 1);
        ls0 += __shfl_xor_sync(0xffffffffu, ls0, 2);
        ls1 += __shfl_xor_sync(0xffffffffu, ls1, 1);
        ls1 += __shfl_xor_sync(0xffffffffu, ls1, 2);
        l0 = l0 * corr0 + ls0;
        l1 = l1 * corr1 + ls1;

        // ---- stage P (tf32) in smem; warp-private rows ----
#pragma unroll
        for (int nt = 0; nt < 8; nt++) {
            *(uint2*)&Ps[(wb + g) * PADA + nt * 8 + 2 * tig] =
                make_uint2(f2tf32(s[nt][0]), f2tf32(s[nt][1]));
            *(uint2*)&Ps[(wb + g + 8) * PADA + nt * 8 + 2 * tig] =
                make_uint2(f2tf32(s[nt][2]), f2tf32(s[nt][3]));
        }
        __syncwarp();

        // rescale O
#pragma unroll
        for (int nt = 0; nt < 8; nt++) {
            o[nt][0] *= corr0; o[nt][1] *= corr0;
            o[nt][2] *= corr1; o[nt][3] *= corr1;
        }

        // ---- O += P V^T (plain tf32), each o[nt] touched once per ks ----
#pragma unroll
        for (int ks = 0; ks < 8; ks++) {
            const uint32_t ko = ks * 32;
            uint32_t a0, a1, a2, a3;
            ldsm_x4(a0, a1, a2, a3, aPs + ko);
#pragma unroll
            for (int ntp = 0; ntp < 4; ntp++) {
                uint32_t b0, b1, b2, b3;
                ldsm_x4(b0, b1, b2, b3,
                        aVt + (uint32_t)(ntp * 16 * PADA) * 4 + ko);
                mma_tf32(o[2 * ntp][0], o[2 * ntp][1], o[2 * ntp][2], o[2 * ntp][3],
                         a0, a1, a2, a3, b0, b1);
                mma_tf32(o[2 * ntp + 1][0], o[2 * ntp + 1][1],
                         o[2 * ntp + 1][2], o[2 * ntp + 1][3],
                         a0, a1, a2, a3, b2, b3);
            }
        }
    }

    // ---- epilogue ----
    const float il0 = 1.f / l0, il1 = 1.f / l1;
    const int r0 = q0 + wb + g, r1 = r0 + 8;
#pragma unroll
    for (int nt = 0; nt < 8; nt++) {
        const int col = h * HEAD_DIM + nt * 8 + 2 * tig;
        *(float2*)(g_o + ((size_t)b * SEQ + r0) * DMODEL + col) =
            make_float2(o[nt][0] * il0, o[nt][1] * il0);
        *(float2*)(g_o + ((size_t)b * SEQ + r1) * DMODEL + col) =
            make_float2(o[nt][2] * il1, o[nt][3] * il1);
    }
}

// ---------------------------------------------------------------------------

extern "C" void kernel_launch(void* const* d_in, const int* in_sizes, int n_in,
                              void* d_out, int out_size) {
    (void)in_sizes; (void)n_in; (void)out_size;
    const float* x      = (const float*)d_in[0];
    const float* w_qkv  = (const float*)d_in[1];
    const float* b_qkv  = (const float*)d_in[2];
    const float* w_proj = (const float*)d_in[3];
    const float* b_proj = (const float*)d_in[4];
    float* out = (float*)d_out;

    cudaFuncSetAttribute(gemm_mma, cudaFuncAttributeMaxDynamicSharedMemorySize,
                         GEMM_SMEM_BYTES);
    cudaFuncSetAttribute(attn_mma, cudaFuncAttributeMaxDynamicSharedMemorySize,
                         ATTN_SMEM_BYTES);

    transpose_kernel<<<dim3(96, 32), dim3(32, 8)>>>(w_qkv, 3072, 0);
    transpose_kernel<<<dim3(32, 32), dim3(32, 8)>>>(w_proj, 1024, 1);

    gemm_mma<<<dim3(24, 64), 256, GEMM_SMEM_BYTES>>>(x, b_qkv, nullptr, 0);

    attn_mma<<<dim3(SEQ / 128, NB_HEADS, BATCH), 256, ATTN_SMEM_BYTES>>>();

    gemm_mma<<<dim3(8, 64), 256, GEMM_SMEM_BYTES>>>(nullptr, b_proj, out, 1);
}

// round 10
// speedup vs baseline: 1.2246x; 1.1770x over previous
#include <cuda_runtime.h>
#include <cuda.h>
#include <cstdint>
#include <math.h>

// ---------------------------------------------------------------------------
// ViT MHA B=8, S=1024, D=1024, H=16, hd=64 (fp32 in/out).
// R9: attention on split-bf16 m16n8k16 mma (hi/lo decomposition, 3-mma per
//     k16 for both QK^T and PV; ldmatrix b16 native, V via ldmatrix.trans).
//     GEMMs unchanged (proven tf32 path).
// ---------------------------------------------------------------------------

#define NB_HEADS 16
#define HEAD_DIM 64
#define SEQ 1024
#define BATCH 8
#define DMODEL 1024

__device__ float g_q[(size_t)BATCH * NB_HEADS * SEQ * HEAD_DIM];
__device__ float g_k[(size_t)BATCH * NB_HEADS * SEQ * HEAD_DIM];
__device__ float g_v[(size_t)BATCH * NB_HEADS * SEQ * HEAD_DIM];
__device__ float g_o[(size_t)BATCH * SEQ * DMODEL];
__device__ float g_wqkvT[(size_t)3072 * 1024];   // [N][K] K-major
__device__ float g_wprojT[(size_t)1024 * 1024];  // [N][K] K-major

// ------------------------------ helpers ------------------------------------
__device__ __forceinline__ uint32_t smem_u32(const void* p) {
    uint32_t a;
    asm("{ .reg .u64 t; cvta.to.shared.u64 t, %1; cvt.u32.u64 %0, t; }"
        : "=r"(a) : "l"(p));
    return a;
}

__device__ __forceinline__ uint32_t f2tf32(float f) {
    uint32_t u;
    asm("cvt.rna.tf32.f32 %0, %1;" : "=r"(u) : "f"(f));
    return u;
}

// pack two floats to bf16x2: lower half = lo, upper half = hi
__device__ __forceinline__ uint32_t packbf(float lo, float hi) {
    uint32_t r;
    asm("cvt.rn.bf16x2.f32 %0, %1, %2;" : "=r"(r) : "f"(hi), "f"(lo));
    return r;
}
__device__ __forceinline__ float bf_lo(uint32_t u) {
    return __uint_as_float(u << 16);
}
__device__ __forceinline__ float bf_hi(uint32_t u) {
    return __uint_as_float(u & 0xffff0000u);
}

__device__ __forceinline__ void cp_async16(uint32_t dst, const void* src) {
    asm volatile("cp.async.ca.shared.global [%0], [%1], 16;"
                 :: "r"(dst), "l"(src) : "memory");
}
__device__ __forceinline__ void cp_commit() {
    asm volatile("cp.async.commit_group;" ::: "memory");
}
__device__ __forceinline__ void cp_wait0() {
    asm volatile("cp.async.wait_group 0;" ::: "memory");
}
__device__ __forceinline__ void cp_wait1() {
    asm volatile("cp.async.wait_group 1;" ::: "memory");
}

__device__ __forceinline__ void mma_tf32(float& c0, float& c1, float& c2, float& c3,
                                         uint32_t a0, uint32_t a1, uint32_t a2,
                                         uint32_t a3, uint32_t b0, uint32_t b1) {
    asm volatile(
        "mma.sync.aligned.m16n8k8.row.col.f32.tf32.tf32.f32 "
        "{%0,%1,%2,%3}, {%4,%5,%6,%7}, {%8,%9}, {%0,%1,%2,%3};"
        : "+f"(c0), "+f"(c1), "+f"(c2), "+f"(c3)
        : "r"(a0), "r"(a1), "r"(a2), "r"(a3), "r"(b0), "r"(b1));
}

__device__ __forceinline__ void mma_bf16(float& c0, float& c1, float& c2, float& c3,
                                         uint32_t a0, uint32_t a1, uint32_t a2,
                                         uint32_t a3, uint32_t b0, uint32_t b1) {
    asm volatile(
        "mma.sync.aligned.m16n8k16.row.col.f32.bf16.bf16.f32 "
        "{%0,%1,%2,%3}, {%4,%5,%6,%7}, {%8,%9}, {%0,%1,%2,%3};"
        : "+f"(c0), "+f"(c1), "+f"(c2), "+f"(c3)
        : "r"(a0), "r"(a1), "r"(a2), "r"(a3), "r"(b0), "r"(b1));
}

__device__ __forceinline__ void ldsm_x4(uint32_t& r0, uint32_t& r1,
                                        uint32_t& r2, uint32_t& r3, uint32_t a) {
    asm volatile("ldmatrix.sync.aligned.m8n8.x4.shared.b16 {%0,%1,%2,%3}, [%4];"
                 : "=r"(r0), "=r"(r1), "=r"(r2), "=r"(r3) : "r"(a));
}
__device__ __forceinline__ void ldsm_x4_t(uint32_t& r0, uint32_t& r1,
                                          uint32_t& r2, uint32_t& r3, uint32_t a) {
    asm volatile("ldmatrix.sync.aligned.m8n8.x4.trans.shared.b16 {%0,%1,%2,%3}, [%4];"
                 : "=r"(r0), "=r"(r1), "=r"(r2), "=r"(r3) : "r"(a));
}

// ---------------------------------------------------------------------------
// Weight transpose: out[n][k] = in[k][n].  in is [1024][C].
// ---------------------------------------------------------------------------
__global__ __launch_bounds__(256) void transpose_kernel(const float* __restrict__ in,
                                                        int C, int which) {
    __shared__ float t[32][33];
    float* out = which ? g_wprojT : g_wqkvT;
    const int R = 1024;
    const int c0 = blockIdx.x * 32, r0 = blockIdx.y * 32;
    const int tx = threadIdx.x, ty = threadIdx.y;  // 32 x 8
#pragma unroll
    for (int i = 0; i < 32; i += 8)
        t[ty + i][tx] = in[(size_t)(r0 + ty + i) * C + c0 + tx];
    __syncthreads();
#pragma unroll
    for (int i = 0; i < 32; i += 8)
        out[(size_t)(c0 + ty + i) * R + r0 + tx] = t[tx][ty + i];
}

// ---------------------------------------------------------------------------
// mma.sync tf32 GEMM (proven): C[128x128] = A x BT^T, K=1024.
// ---------------------------------------------------------------------------
#define PAD 36
#define GEMM_SMEM_BYTES (2 * 2 * 128 * PAD * 4)

__global__ __launch_bounds__(256) void gemm_mma(const float* __restrict__ A_ext,
                                                const float* __restrict__ bias,
                                                float* __restrict__ Cout, int mode) {
    extern __shared__ __align__(16) float sm[];
    float* As = sm;
    float* Bs = sm + 2 * 128 * PAD;
    const uint32_t sA = smem_u32(As), sB = smem_u32(Bs);

    const float* A  = mode ? g_o      : A_ext;
    const float* BT = mode ? g_wprojT : g_wqkvT;

    const int m0 = blockIdx.y * 128;
    const int n0 = blockIdx.x * 128;
    const int tid = threadIdx.x;
    const int warp = tid >> 5, lane = tid & 31;
    const int g = lane >> 2, tig = lane & 3;
    const int wm = (warp >> 2) * 64;
    const int wn = (warp & 3) * 32;

    float c[4][4][4];
#pragma unroll
    for (int i = 0; i < 4; i++)
#pragma unroll
        for (int j = 0; j < 4; j++)
#pragma unroll
            for (int r = 0; r < 4; r++) c[i][j][r] = 0.f;

    auto prefetch = [&](int buf, int kc) {
        const float* Ag = A  + (size_t)m0 * 1024 + kc * 32;
        const float* Bg = BT + (size_t)n0 * 1024 + kc * 32;
        const uint32_t aBase = sA + buf * 128 * PAD * 4;
        const uint32_t bBase = sB + buf * 128 * PAD * 4;
#pragma unroll
        for (int i = 0; i < 4; i++) {
            const int idx = tid + i * 256;
            const int row = idx >> 3, c4 = idx & 7;
            const uint32_t so = (uint32_t)(row * PAD + c4 * 4) * 4;
            cp_async16(aBase + so, Ag + (size_t)row * 1024 + c4 * 4);
            cp_async16(bBase + so, Bg + (size_t)row * 1024 + c4 * 4);
        }
        cp_commit();
    };

    prefetch(0, 0);

    for (int kc = 0; kc < 32; kc++) {
        const int p = kc & 1;
        cp_wait0();
        __syncthreads();
        if (kc < 31) prefetch(p ^ 1, kc + 1);

        const float* Ab = As + p * 128 * PAD;
        const float* Bb = Bs + p * 128 * PAD;

#pragma unroll
        for (int ks = 0; ks < 4; ks++) {
            const int kk = ks * 8;
            uint32_t a[4][4], b[4][2];
#pragma unroll
            for (int mt = 0; mt < 4; mt++) {
                const int r0 = wm + mt * 16 + g;
                a[mt][0] = f2tf32(Ab[r0 * PAD + kk + tig]);
                a[mt][1] = f2tf32(Ab[(r0 + 8) * PAD + kk + tig]);
                a[mt][2] = f2tf32(Ab[r0 * PAD + kk + tig + 4]);
                a[mt][3] = f2tf32(Ab[(r0 + 8) * PAD + kk + tig + 4]);
            }
#pragma unroll
            for (int nt = 0; nt < 4; nt++) {
                const int nr = wn + nt * 8 + g;
                b[nt][0] = f2tf32(Bb[nr * PAD + kk + tig]);
                b[nt][1] = f2tf32(Bb[nr * PAD + kk + tig + 4]);
            }
#pragma unroll
            for (int mt = 0; mt < 4; mt++)
#pragma unroll
                for (int nt = 0; nt < 4; nt++)
                    mma_tf32(c[mt][nt][0], c[mt][nt][1], c[mt][nt][2], c[mt][nt][3],
                             a[mt][0], a[mt][1], a[mt][2], a[mt][3],
                             b[nt][0], b[nt][1]);
        }
        __syncthreads();
    }

#pragma unroll
    for (int mt = 0; mt < 4; mt++) {
#pragma unroll
        for (int nt = 0; nt < 4; nt++) {
            const int rowA = m0 + wm + mt * 16 + g;
            const int rowB = rowA + 8;
            const int n = n0 + wn + nt * 8 + 2 * tig;
            const float b0 = bias[n], b1 = bias[n + 1];
            if (mode == 1) {
                *(float2*)(Cout + (size_t)rowA * 1024 + n) =
                    make_float2(c[mt][nt][0] + b0, c[mt][nt][1] + b1);
                *(float2*)(Cout + (size_t)rowB * 1024 + n) =
                    make_float2(c[mt][nt][2] + b0, c[mt][nt][3] + b1);
            } else {
                const int which = n >> 10;
                const int nm = n & 1023;
                const int h = nm >> 6, dd = nm & 63;
                float* dst = (which == 0) ? g_q : (which == 1) ? g_k : g_v;
                const float sc = (which == 0) ? 0.125f : 1.f;
                const int bA = rowA >> 10, sAr = rowA & 1023;
                const int bB = rowB >> 10, sBr = rowB & 1023;
                const size_t offA =
                    (((size_t)(bA * NB_HEADS + h) * SEQ) + sAr) * HEAD_DIM + dd;
                const size_t offB =
                    (((size_t)(bB * NB_HEADS + h) * SEQ) + sBr) * HEAD_DIM + dd;
                *(float2*)(dst + offA) =
                    make_float2((c[mt][nt][0] + b0) * sc, (c[mt][nt][1] + b1) * sc);
                *(float2*)(dst + offB) =
                    make_float2((c[mt][nt][2] + b0) * sc, (c[mt][nt][3] + b1) * sc);
            }
        }
    }
}

// ---------------------------------------------------------------------------
// Split-bf16 flash attention.
// Block = (128 queries) x (b,h). 256 threads / 8 warps, warp owns 16 q-rows.
// All operands bf16 hi/lo in smem, rows padded to 72 elems (144 B = 9*16B).
// QK^T and PV each: 3 x mma.m16n8k16 per k16 (hh + h*lo + lo*h).
// ---------------------------------------------------------------------------
#define PADA 68   // fp32 staging stride (words)
#define PADB 72   // bf16 row stride (elems) -> 144 bytes
#define RB   144  // row bytes

#define OB_QH 0
#define OB_QL (OB_QH + 128 * RB)
#define OB_KH (OB_QL + 128 * RB)
#define OB_KL (OB_KH + 64 * RB)
#define OB_VH (OB_KL + 64 * RB)
#define OB_VL (OB_VH + 64 * RB)
#define OB_PH (OB_VL + 64 * RB)
#define OB_PL (OB_PH + 128 * RB)
#define OB_ST (OB_PL + 128 * RB)
#define ATTN_SMEM_BYTES (OB_ST + 2 * 128 * PADA * 4)

__global__ __launch_bounds__(256, 1) void attn_mma() {
    extern __shared__ __align__(16) char smc[];
    const uint32_t sb = smem_u32(smc);
    float* St[2] = {(float*)(smc + OB_ST), (float*)(smc + OB_ST + 128 * PADA * 4)};

    const int tid = threadIdx.x;
    const int warp = tid >> 5, lane = tid & 31;
    const int g = lane >> 2, tig = lane & 3;
    const int wb = warp * 16;

    const int q0 = blockIdx.x * 128;
    const int h = blockIdx.y, b = blockIdx.z;
    const size_t bh = (size_t)(b * NB_HEADS + h) * SEQ * HEAD_DIM;
    const float* qb = g_q + bh;
    const float* kb = g_k + bh;
    const float* vb = g_v + bh;

    auto issue_tile = [&](int k0, float* Stp) {
        const uint32_t sSt = smem_u32(Stp);
#pragma unroll
        for (int i = 0; i < 4; i++) {
            const int idx = tid + i * 256;
            const int row = idx >> 4, c4 = idx & 15;
            cp_async16(sSt + (uint32_t)(row * PADA + c4 * 4) * 4,
                       kb + (size_t)(k0 + row) * 64 + c4 * 4);
        }
#pragma unroll
        for (int i = 0; i < 4; i++) {
            const int idx = tid + i * 256;
            const int row = idx >> 4, c4 = idx & 15;
            cp_async16(sSt + (uint32_t)((64 + row) * PADA + c4 * 4) * 4,
                       vb + (size_t)(k0 + row) * 64 + c4 * 4);
        }
        cp_commit();
    };

    // split-convert a float4 -> (hi u32x2, lo u32x2)
    auto split4 = [](const float4 v, uint2& hi, uint2& lo) {
        const uint32_t h01 = packbf(v.x, v.y);
        const uint32_t h23 = packbf(v.z, v.w);
        const uint32_t l01 = packbf(v.x - bf_lo(h01), v.y - bf_hi(h01));
        const uint32_t l23 = packbf(v.z - bf_lo(h23), v.w - bf_hi(h23));
        hi = make_uint2(h01, h23);
        lo = make_uint2(l01, l23);
    };

    // ---- prologue: stage raw Q (fp32) into PH/PL area, prefetch tile 0 ----
    {
        float* Qstage = (float*)(smc + OB_PH);
        const uint32_t sQst = smem_u32(Qstage);
#pragma unroll
        for (int i = 0; i < 8; i++) {
            const int idx = tid + i * 256;
            const int row = idx >> 4, c4 = idx & 15;
            cp_async16(sQst + (uint32_t)(row * PADA + c4 * 4) * 4,
                       qb + (size_t)(q0 + row) * 64 + c4 * 4);
        }
        cp_commit();
        issue_tile(0, St[0]);
        cp_wait1();
        __syncthreads();
#pragma unroll
        for (int i = 0; i < 8; i++) {
            const int idx = tid + i * 256;
            const int row = idx >> 4, c4 = idx & 15;
            const float4 v = *(const float4*)&Qstage[row * PADA + c4 * 4];
            uint2 hi, lo;
            split4(v, hi, lo);
            *(uint2*)(smc + OB_QH + row * RB + c4 * 8) = hi;
            *(uint2*)(smc + OB_QL + row * RB + c4 * 8) = lo;
        }
    }

    // ldmatrix per-lane base addresses
    const int rA = lane & 15;                 // A-frag rows (Q, P)
    const int kA = (lane >> 4) << 4;          // A-frag k byte offset
    const int rK = ((lane >> 4) << 3) + (lane & 7);       // K B-frag row
    const int kK = ((lane >> 3) & 1) << 4;                // K B-frag k byte
    const int rV = lane & 15;                 // V trans rows (keys)
    const int dV = (lane >> 4) << 4;          // V d byte offset

    const uint32_t aQH = sb + OB_QH + (wb + rA) * RB + kA;
    const uint32_t aQL = sb + OB_QL + (wb + rA) * RB + kA;
    const uint32_t aPH = sb + OB_PH + (wb + rA) * RB + kA;
    const uint32_t aPL = sb + OB_PL + (wb + rA) * RB + kA;
    const uint32_t aKH = sb + OB_KH + rK * RB + kK;
    const uint32_t aKL = sb + OB_KL + rK * RB + kK;
    const uint32_t aVH = sb + OB_VH + rV * RB + dV;
    const uint32_t aVL = sb + OB_VL + rV * RB + dV;

    float o[8][4];
#pragma unroll
    for (int nt = 0; nt < 8; nt++)
#pragma unroll
        for (int r = 0; r < 4; r++) o[nt][r] = 0.f;
    float m0 = -1e30f, m1 = -1e30f, l0 = 0.f, l1 = 0.f;

    for (int kb0 = 0; kb0 < 16; kb0++) {
        const int p = kb0 & 1;
        float* Stc = St[p];
        cp_wait0();
        __syncthreads();   // prev iter reads done; Q/K/V convert targets free

        // ---- split-convert K (St rows 0-63) and V (St rows 64-127) ----
#pragma unroll
        for (int i = 0; i < 4; i++) {
            const int idx = tid + i * 256;
            const int row = idx >> 4, c4 = idx & 15;
            uint2 hi, lo;
            split4(*(const float4*)&Stc[row * PADA + c4 * 4], hi, lo);
            *(uint2*)(smc + OB_KH + row * RB + c4 * 8) = hi;
            *(uint2*)(smc + OB_KL + row * RB + c4 * 8) = lo;
            split4(*(const float4*)&Stc[(64 + row) * PADA + c4 * 4], hi, lo);
            *(uint2*)(smc + OB_VH + row * RB + c4 * 8) = hi;
            *(uint2*)(smc + OB_VL + row * RB + c4 * 8) = lo;
        }

        if (kb0 < 15) issue_tile((kb0 + 1) * 64, St[p ^ 1]);
        __syncthreads();

        // ---- S = Q K^T : 3 bf16 mma per k16 ----
        float s[8][4];
#pragma unroll
        for (int nt = 0; nt < 8; nt++)
#pragma unroll
            for (int r = 0; r < 4; r++) s[nt][r] = 0.f;

#pragma unroll
        for (int ks = 0; ks < 4; ks++) {
            const uint32_t ko = ks * 32;   // k16 = 32 bytes
            uint32_t ah0, ah1, ah2, ah3, al0, al1, al2, al3;
            ldsm_x4(ah0, ah1, ah2, ah3, aQH + ko);
            ldsm_x4(al0, al1, al2, al3, aQL + ko);
#pragma unroll
            for (int ntp = 0; ntp < 4; ntp++) {
                const uint32_t no = (uint32_t)(ntp * 16 * RB) + ko;
                uint32_t kh0, kh1, kh2, kh3, kl0, kl1, kl2, kl3;
                ldsm_x4(kh0, kh1, kh2, kh3, aKH + no);
                ldsm_x4(kl0, kl1, kl2, kl3, aKL + no);
                const int n0t = 2 * ntp, n1t = 2 * ntp + 1;
                mma_bf16(s[n0t][0], s[n0t][1], s[n0t][2], s[n0t][3],
                         ah0, ah1, ah2, ah3, kl0, kl1);
                mma_bf16(s[n0t][0], s[n0t][1], s[n0t][2], s[n0t][3],
                         al0, al1, al2, al3, kh0, kh1);
                mma_bf16(s[n0t][0], s[n0t][1], s[n0t][2], s[n0t][3],
                         ah0, ah1, ah2, ah3, kh0, kh1);
                mma_bf16(s[n1t][0], s[n1t][1], s[n1t][2], s[n1t][3],
                         ah0, ah1, ah2, ah3, kl2, kl3);
                mma_bf16(s[n1t][0], s[n1t][1], s[n1t][2], s[n1t][3],
                         al0, al1, al2, al3, kh2, kh3);
                mma_bf16(s[n1t][0], s[n1t][1], s[n1t][2], s[n1t][3],
                         ah0, ah1, ah2, ah3, kh2, kh3);
            }
        }

        // ---- fragment online softmax ----
        float rmax0 = -1e30f, rmax1 = -1e30f;
#pragma unroll
        for (int nt = 0; nt < 8; nt++) {
            rmax0 = fmaxf(rmax0, fmaxf(s[nt][0], s[nt][1]));
            rmax1 = fmaxf(rmax1, fmaxf(s[nt][2], s[nt][3]));
        }
        rmax0 = fmaxf(rmax0, __shfl_xor_sync(0xffffffffu, rmax0, 1));
        rmax0 = fmaxf(rmax0, __shfl_xor_sync(0xffffffffu, rmax0, 2));
        rmax1 = fmaxf(rmax1, __shfl_xor_sync(0xffffffffu, rmax1, 1));
        rmax1 = fmaxf(rmax1, __shfl_xor_sync(0xffffffffu, rmax1, 2));

        const float mn0 = fmaxf(m0, rmax0), mn1 = fmaxf(m1, rmax1);
        const float corr0 = __expf(m0 - mn0), corr1 = __expf(m1 - mn1);
        m0 = mn0; m1 = mn1;

        float ls0 = 0.f, ls1 = 0.f;
#pragma unroll
        for (int nt = 0; nt < 8; nt++) {
            s[nt][0] = __expf(s[nt][0] - mn0);
            s[nt][1] = __expf(s[nt][1] - mn0);
            s[nt][2] = __expf(s[nt][2] - mn1);
            s[nt][3] = __expf(s[nt][3] - mn1);
            ls0 += s[nt][0] + s[nt][1];
            ls1 += s[nt][2] + s[nt][3];
        }
        ls0 += __shfl_xor_sync(0xffffffffu, ls0, 1);
        ls0 += __shfl_xor_sync(0xffffffffu, ls0, 2);
        ls1 += __shfl_xor_sync(0xffffffffu, ls1, 1);
        ls1 += __shfl_xor_sync(0xffffffffu, ls1, 2);
        l0 = l0 * corr0 + ls0;
        l1 = l1 * corr1 + ls1;

        // ---- stage P as bf16 hi/lo (warp-private rows) ----
#pragma unroll
        for (int nt = 0; nt < 8; nt++) {
            const int cby = nt * 16 + tig * 4;   // (nt*8 + 2tig) * 2 bytes
            uint32_t ph = packbf(s[nt][0], s[nt][1]);
            uint32_t pl = packbf(s[nt][0] - bf_lo(ph), s[nt][1] - bf_hi(ph));
            *(uint32_t*)(smc + OB_PH + (wb + g) * RB + cby) = ph;
            *(uint32_t*)(smc + OB_PL + (wb + g) * RB + cby) = pl;
            ph = packbf(s[nt][2], s[nt][3]);
            pl = packbf(s[nt][2] - bf_lo(ph), s[nt][3] - bf_hi(ph));
            *(uint32_t*)(smc + OB_PH + (wb + g + 8) * RB + cby) = ph;
            *(uint32_t*)(smc + OB_PL + (wb + g + 8) * RB + cby) = pl;
        }
        __syncwarp();

        // rescale O
#pragma unroll
        for (int nt = 0; nt < 8; nt++) {
            o[nt][0] *= corr0; o[nt][1] *= corr0;
            o[nt][2] *= corr1; o[nt][3] *= corr1;
        }

        // ---- O += P V : 3 bf16 mma per k16, V via ldmatrix.trans ----
#pragma unroll
        for (int ks = 0; ks < 4; ks++) {
            const uint32_t ko = ks * 32;
            uint32_t ph0, ph1, ph2, ph3, pl0, pl1, pl2, pl3;
            ldsm_x4(ph0, ph1, ph2, ph3, aPH + ko);
            ldsm_x4(pl0, pl1, pl2, pl3, aPL + ko);
#pragma unroll
            for (int ntp = 0; ntp < 4; ntp++) {
                const uint32_t vo = (uint32_t)(ks * 16 * RB) + ntp * 32;
                uint32_t vh0, vh1, vh2, vh3, vl0, vl1, vl2, vl3;
                ldsm_x4_t(vh0, vh1, vh2, vh3, aVH + vo);
                ldsm_x4_t(vl0, vl1, vl2, vl3, aVL + vo);
                const int n0t = 2 * ntp, n1t = 2 * ntp + 1;
                mma_bf16(o[n0t][0], o[n0t][1], o[n0t][2], o[n0t][3],
                         ph0, ph1, ph2, ph3, vl0, vl1);
                mma_bf16(o[n0t][0], o[n0t][1], o[n0t][2], o[n0t][3],
                         pl0, pl1, pl2, pl3, vh0, vh1);
                mma_bf16(o[n0t][0], o[n0t][1], o[n0t][2], o[n0t][3],
                         ph0, ph1, ph2, ph3, vh0, vh1);
                mma_bf16(o[n1t][0], o[n1t][1], o[n1t][2], o[n1t][3],
                         ph0, ph1, ph2, ph3, vl2, vl3);
                mma_bf16(o[n1t][0], o[n1t][1], o[n1t][2], o[n1t][3],
                         pl0, pl1, pl2, pl3, vh2, vh3);
                mma_bf16(o[n1t][0], o[n1t][1], o[n1t][2], o[n1t][3],
                         ph0, ph1, ph2, ph3, vh2, vh3);
            }
        }
    }

    // ---- epilogue ----
    const float il0 = 1.f / l0, il1 = 1.f / l1;
    const int r0 = q0 + wb + g, r1 = r0 + 8;
#pragma unroll
    for (int nt = 0; nt < 8; nt++) {
        const int col = h * HEAD_DIM + nt * 8 + 2 * tig;
        *(float2*)(g_o + ((size_t)b * SEQ + r0) * DMODEL + col) =
            make_float2(o[nt][0] * il0, o[nt][1] * il0);
        *(float2*)(g_o + ((size_t)b * SEQ + r1) * DMODEL + col) =
            make_float2(o[nt][2] * il1, o[nt][3] * il1);
    }
}

// ---------------------------------------------------------------------------

extern "C" void kernel_launch(void* const* d_in, const int* in_sizes, int n_in,
                              void* d_out, int out_size) {
    (void)in_sizes; (void)n_in; (void)out_size;
    const float* x      = (const float*)d_in[0];
    const float* w_qkv  = (const float*)d_in[1];
    const float* b_qkv  = (const float*)d_in[2];
    const float* w_proj = (const float*)d_in[3];
    const float* b_proj = (const float*)d_in[4];
    float* out = (float*)d_out;

    cudaFuncSetAttribute(gemm_mma, cudaFuncAttributeMaxDynamicSharedMemorySize,
                         GEMM_SMEM_BYTES);
    cudaFuncSetAttribute(attn_mma, cudaFuncAttributeMaxDynamicSharedMemorySize,
                         ATTN_SMEM_BYTES);

    transpose_kernel<<<dim3(96, 32), dim3(32, 8)>>>(w_qkv, 3072, 0);
    transpose_kernel<<<dim3(32, 32), dim3(32, 8)>>>(w_proj, 1024, 1);

    gemm_mma<<<dim3(24, 64), 256, GEMM_SMEM_BYTES>>>(x, b_qkv, nullptr, 0);

    attn_mma<<<dim3(SEQ / 128, NB_HEADS, BATCH), 256, ATTN_SMEM_BYTES>>>();

    gemm_mma<<<dim3(8, 64), 256, GEMM_SMEM_BYTES>>>(nullptr, b_proj, out, 1);
}